// round 3
// baseline (speedup 1.0000x reference)
#include <cuda_runtime.h>
#include <math.h>

#define Bz 32
#define Tz 1024
#define Dz 256
#define Hz 256
#define NG 1024  // 4*H

// ---------------- scratch (device globals: no allocation allowed) ----------
__device__ __align__(16) float g_xp1[2][Tz][Bz][NG];   // layer1 gate preacts (f,b)
__device__ __align__(16) float g_xp2[2][Tz][Bz][NG];   // layer2 gate preacts (f,b)
__device__ __align__(16) float g_h1 [2][Tz][Bz][Hz];   // layer1 hidden states (orig-time order)
__device__ __align__(16) float g_hbuf1[2][2][Bz*Hz];   // ping-pong h, layer1 (dir, buf)
__device__ __align__(16) float g_hbuf2[2][2][Bz*Hz];   // ping-pong h, layer2
__device__ unsigned int g_barcnt[4];
__device__ unsigned int g_bargen[4];

// ---------------- sync helpers ---------------------------------------------
__device__ __forceinline__ void st_release(unsigned int* p, unsigned int v) {
    asm volatile("st.global.release.gpu.u32 [%0], %1;" :: "l"(p), "r"(v) : "memory");
}
__device__ __forceinline__ unsigned int ld_acquire(unsigned int* p) {
    unsigned int v;
    asm volatile("ld.global.acquire.gpu.u32 %0, [%1];" : "=r"(v) : "l"(p) : "memory");
    return v;
}
__device__ __forceinline__ float fast_sigmoid(float x) {
    return __fdividef(1.f, 1.f + __expf(-x));
}

// ---------------- init: reset barriers + zero h0 ----------------------------
__global__ void k_init() {
    int tid = blockIdx.x * blockDim.x + threadIdx.x;
    if (tid < 4) { g_barcnt[tid] = 0; g_bargen[tid] = 0; }
    if (tid < Bz * Hz) {
        g_hbuf1[0][0][tid] = 0.f;
        g_hbuf1[1][0][tid] = 0.f;
        g_hbuf2[0][0][tid] = 0.f;
        g_hbuf2[1][0][tid] = 0.f;
    }
}

// ---------------- GEMM: xp = A @ W (+bias) ---------------------------------
// out[dir][t][b][n] = sum_k A(t,b,k) * W[g][k][h]  (n = g*256+h)
// layer==1: A = x (rev for dir 1), weights Wx*, bias added.
// layer==2: A = [x ; g_h1[dir]] (both rev for dir 1), weights Wx*,Wh*, no bias.
#define KC 32
__global__ void __launch_bounds__(256, 2) k_gemm(
    const float* __restrict__ x,
    const float* __restrict__ Wx0, const float* __restrict__ Wx1,
    const float* __restrict__ Wh0, const float* __restrict__ Wh1,
    const float* __restrict__ bias0, const float* __restrict__ bias1,
    int layer)
{
    const int dir = blockIdx.z;
    const float* Wxd  = dir ? Wx1 : Wx0;
    const float* Whd  = dir ? Wh1 : Wh0;
    const float* bias = dir ? bias1 : bias0;
    const float* hsrc = &g_h1[dir][0][0][0];
    float* out = (layer == 1) ? &g_xp1[dir][0][0][0] : &g_xp2[dir][0][0][0];

    const int m0 = blockIdx.y * 128;
    const int n0 = blockIdx.x * 128;
    const int g  = n0 >> 8;
    const int hbase = n0 & 255;

    __shared__ __align__(16) float As[128][36];
    __shared__ __align__(16) float Bs[KC][128];

    const int tid = threadIdx.x;
    const int tx = tid & 15, ty = tid >> 4;

    float acc[8][8];
#pragma unroll
    for (int i = 0; i < 8; ++i)
#pragma unroll
        for (int j = 0; j < 8; ++j) acc[i][j] = 0.f;

    const int nsrc = (layer == 1) ? 1 : 2;
    for (int src = 0; src < nsrc; ++src) {
        const float* Wsrc = (src == 0) ? Wxd : Whd;
        for (int kc = 0; kc < 256; kc += KC) {
            // load A tile: 128 rows x 32 k
#pragma unroll
            for (int i = 0; i < 4; ++i) {
                int idx = tid + i * 256;          // 0..1023 float4 slots
                int row = idx >> 3;
                int kq  = (idx & 7) << 2;
                int m = m0 + row;
                int t = m >> 5, b = m & 31;
                int tt = dir ? (Tz - 1 - t) : t;
                const float* ap;
                if (src == 0) ap = x    + ((size_t)b * Tz + tt) * Dz + kc + kq;
                else          ap = hsrc + ((size_t)tt * Bz + b) * Hz + kc + kq;
                float4 v = *(const float4*)ap;
                *(float4*)&As[row][kq] = v;
            }
            // load B tile: 32 k x 128 n
#pragma unroll
            for (int i = 0; i < 4; ++i) {
                int idx = tid + i * 256;
                int k  = idx >> 5;
                int c4 = (idx & 31) << 2;
                float4 v = *(const float4*)(Wsrc + (size_t)g * 65536 +
                                            (size_t)(kc + k) * 256 + hbase + c4);
                *(float4*)&Bs[k][c4] = v;
            }
            __syncthreads();
#pragma unroll
            for (int k = 0; k < KC; ++k) {
                float a[8];
#pragma unroll
                for (int i = 0; i < 8; ++i) a[i] = As[ty + i * 16][k];
                float4 b0 = *(const float4*)&Bs[k][tx * 4];
                float4 b1 = *(const float4*)&Bs[k][64 + tx * 4];
                float bb[8] = {b0.x, b0.y, b0.z, b0.w, b1.x, b1.y, b1.z, b1.w};
#pragma unroll
                for (int i = 0; i < 8; ++i)
#pragma unroll
                    for (int j = 0; j < 8; ++j) acc[i][j] += a[i] * bb[j];
            }
            __syncthreads();
        }
    }

    float bv[8];
#pragma unroll
    for (int j = 0; j < 8; ++j) bv[j] = 0.f;
    if (layer == 1) {
#pragma unroll
        for (int j = 0; j < 8; ++j) {
            int n = n0 + (j >> 2) * 64 + tx * 4 + (j & 3);
            bv[j] = bias[n];
        }
    }
#pragma unroll
    for (int i = 0; i < 8; ++i) {
        int m = m0 + ty + i * 16;
        size_t ro = (size_t)m * NG;
        float4 v0 = make_float4(acc[i][0] + bv[0], acc[i][1] + bv[1],
                                acc[i][2] + bv[2], acc[i][3] + bv[3]);
        float4 v1 = make_float4(acc[i][4] + bv[4], acc[i][5] + bv[5],
                                acc[i][6] + bv[6], acc[i][7] + bv[7]);
        *(float4*)&out[ro + n0 + tx * 4]      = v0;
        *(float4*)&out[ro + n0 + 64 + tx * 4] = v1;
    }
}

// ---------------- layer1 recurrence (persistent, grid barrier) --------------
// grid = 128 CTAs: CTA = (dir<<6) | cg ; owns h-cols [cg*4, cg*4+4)
__global__ void __launch_bounds__(256) k_recur1(
    const float* __restrict__ Uf, const float* __restrict__ Ub)
{
    const int dir = blockIdx.x >> 6;
    const int cg  = blockIdx.x & 63;
    const float* U  = dir ? Ub : Uf;
    const float* xp = &g_xp1[dir][0][0][0];
    float* hs  = &g_h1[dir][0][0][0];
    float* hb0 = g_hbuf1[dir][0];
    float* hb1 = g_hbuf1[dir][1];
    unsigned int* bcnt = &g_barcnt[dir];
    unsigned int* bgen = &g_bargen[dir];

    __shared__ __align__(16) float sU[256][16];     // [k][gc], gc = g*4+oc
    __shared__ float sPart[8][16][32];              // [warp][gc][b]
    __shared__ float sGate[16][32];                 // [gc][b]

    const int tid = threadIdx.x, lane = tid & 31, w = tid >> 5;

    for (int i = tid; i < 4096; i += 256) {
        int k = i >> 4, gc = i & 15;
        sU[k][gc] = U[(size_t)(gc >> 2) * 65536 + (size_t)k * 256 + cg * 4 + (gc & 3)];
    }
    __syncthreads();

    float c_state = 0.f;
    const int cb = tid >> 2, coc = tid & 3;         // valid for tid<128
    const int outcol = cg * 4 + coc;

    const int rb = tid & 31, rg0 = tid >> 5, rg1 = (tid >> 5) + 8;

    for (int t = 0; t < Tz; ++t) {
        const float* hrd = (t & 1) ? hb1 : hb0;
        float* hwr       = (t & 1) ? hb0 : hb1;

        // prefetch xp for the reduce phase
        size_t xbase = ((size_t)t * 32 + rb) * NG + (size_t)cg * 4;
        float xv0 = xp[xbase + (rg0 >> 2) * 256 + (rg0 & 3)];
        float xv1 = xp[xbase + (rg1 >> 2) * 256 + (rg1 & 3)];

        // h into registers: lane = b, warp = k-chunk
        float hreg[32];
        const float4* hp = (const float4*)(hrd + lane * 256 + w * 32);
#pragma unroll
        for (int j = 0; j < 8; ++j) {
            float4 v = hp[j];
            hreg[4*j] = v.x; hreg[4*j+1] = v.y; hreg[4*j+2] = v.z; hreg[4*j+3] = v.w;
        }

        float acc[16];
#pragma unroll
        for (int c = 0; c < 16; ++c) acc[c] = 0.f;
#pragma unroll
        for (int k = 0; k < 32; ++k) {
            int kk = w * 32 + k;
            float4 u0 = *(const float4*)&sU[kk][0];
            float4 u1 = *(const float4*)&sU[kk][4];
            float4 u2 = *(const float4*)&sU[kk][8];
            float4 u3 = *(const float4*)&sU[kk][12];
            float h = hreg[k];
            acc[0]  += u0.x * h; acc[1]  += u0.y * h; acc[2]  += u0.z * h; acc[3]  += u0.w * h;
            acc[4]  += u1.x * h; acc[5]  += u1.y * h; acc[6]  += u1.z * h; acc[7]  += u1.w * h;
            acc[8]  += u2.x * h; acc[9]  += u2.y * h; acc[10] += u2.z * h; acc[11] += u2.w * h;
            acc[12] += u3.x * h; acc[13] += u3.y * h; acc[14] += u3.z * h; acc[15] += u3.w * h;
        }
#pragma unroll
        for (int c = 0; c < 16; ++c) sPart[w][c][lane] = acc[c];
        __syncthreads();

        // reduce across warps + sigmoid (2 items/thread)
        float p0 = xv0, p1 = xv1;
#pragma unroll
        for (int ww = 0; ww < 8; ++ww) { p0 += sPart[ww][rg0][rb]; p1 += sPart[ww][rg1][rb]; }
        sGate[rg0][rb] = fast_sigmoid(p0);
        sGate[rg1][rb] = fast_sigmoid(p1);
        __syncthreads();

        // cell update: thread (b, oc) keeps c in a register across all steps
        if (tid < 128) {
            float ig = sGate[0  + coc][cb];
            float fg = sGate[4  + coc][cb];
            float gg = sGate[8  + coc][cb];
            float og = sGate[12 + coc][cb];
            c_state = fg + c_state + ig * gg;
            float hn = og + tanhf(c_state);
            hwr[cb * 256 + outcol] = hn;
            int tout = dir ? (Tz - 1 - t) : t;
            hs[((size_t)tout * 32 + cb) * 256 + outcol] = hn;
        }
        __threadfence();
        __syncthreads();
        if (tid == 0) {
            unsigned int a = atomicAdd(bcnt, 1);
            if (a == 63) {
                *bcnt = 0;
                __threadfence();
                st_release(bgen, (unsigned)t + 1);
            } else {
                while (ld_acquire(bgen) <= (unsigned)t) { }
            }
        }
        __syncthreads();
    }
}

// ---------------- layer2 recurrence -----------------------------------------
// hu = h @ U2[0] + b2[0]; gates[g] = sigmoid(xp2[t,b,g,o] + hu[b,o])
__global__ void __launch_bounds__(256) k_recur2(
    const float* __restrict__ Uf, const float* __restrict__ Ub,
    const float* __restrict__ b2f, const float* __restrict__ b2b,
    float* __restrict__ dout)
{
    const int dir = blockIdx.x >> 6;
    const int cg  = blockIdx.x & 63;
    const float* U  = dir ? Ub : Uf;      // only U[0] slice used
    const float* b2 = dir ? b2b : b2f;    // only b[0] used
    const float* xp = &g_xp2[dir][0][0][0];
    float* hb0 = g_hbuf2[dir][0];
    float* hb1 = g_hbuf2[dir][1];
    unsigned int* bcnt = &g_barcnt[2 + dir];
    unsigned int* bgen = &g_bargen[2 + dir];
    float* ynet = dout + (size_t)Bz * 512;          // y_net2 region
    float* yt   = dout;                             // y_t2 region

    __shared__ __align__(16) float sU[256][4];      // [k][oc] from U[0]
    __shared__ float sPart[8][4][32];               // [warp][oc][b]

    const int tid = threadIdx.x, lane = tid & 31, w = tid >> 5;

    for (int i = tid; i < 1024; i += 256) {
        int k = i >> 2, oc = i & 3;
        sU[k][oc] = U[(size_t)k * 256 + cg * 4 + oc];
    }
    __syncthreads();

    float c_state = 0.f;
    const int cb = tid >> 2, coc = tid & 3;
    const int outcol = cg * 4 + coc;
    const float biasv = b2[outcol];

    for (int t = 0; t < Tz; ++t) {
        const float* hrd = (t & 1) ? hb1 : hb0;
        float* hwr       = (t & 1) ? hb0 : hb1;

        // prefetch xp gate values for cell threads
        float xq0 = 0.f, xq1 = 0.f, xq2 = 0.f, xq3 = 0.f;
        if (tid < 128) {
            size_t xb = ((size_t)t * 32 + cb) * NG + outcol;
            xq0 = xp[xb];
            xq1 = xp[xb + 256];
            xq2 = xp[xb + 512];
            xq3 = xp[xb + 768];
        }

        float hreg[32];
        const float4* hp = (const float4*)(hrd + lane * 256 + w * 32);
#pragma unroll
        for (int j = 0; j < 8; ++j) {
            float4 v = hp[j];
            hreg[4*j] = v.x; hreg[4*j+1] = v.y; hreg[4*j+2] = v.z; hreg[4*j+3] = v.w;
        }

        float a0 = 0.f, a1 = 0.f, a2 = 0.f, a3 = 0.f;
#pragma unroll
        for (int k = 0; k < 32; ++k) {
            float4 u = *(const float4*)&sU[w * 32 + k][0];
            float h = hreg[k];
            a0 += u.x * h; a1 += u.y * h; a2 += u.z * h; a3 += u.w * h;
        }
        sPart[w][0][lane] = a0;
        sPart[w][1][lane] = a1;
        sPart[w][2][lane] = a2;
        sPart[w][3][lane] = a3;
        __syncthreads();

        if (tid < 128) {
            float hu = biasv;
#pragma unroll
            for (int ww = 0; ww < 8; ++ww) hu += sPart[ww][coc][cb];
            float ig = fast_sigmoid(xq0 + hu);
            float fg = fast_sigmoid(xq1 + hu);
            float gg = fast_sigmoid(xq2 + hu);
            float og = fast_sigmoid(xq3 + hu);
            c_state = fg + c_state + ig * gg;
            float hn = og + tanhf(c_state);
            hwr[cb * 256 + outcol] = hn;
            if (dir == 0)
                ynet[((size_t)cb * Tz + t) * 512 + outcol] = hn;
            else
                ynet[((size_t)cb * Tz + (Tz - 1 - t)) * 512 + 256 + outcol] = hn;
            if (t == Tz - 1)
                yt[(size_t)cb * 512 + dir * 256 + outcol] = hn;
        }
        __threadfence();
        __syncthreads();
        if (tid == 0) {
            unsigned int a = atomicAdd(bcnt, 1);
            if (a == 63) {
                *bcnt = 0;
                __threadfence();
                st_release(bgen, (unsigned)t + 1);
            } else {
                while (ld_acquire(bgen) <= (unsigned)t) { }
            }
        }
        __syncthreads();
    }
}

// ---------------- launch -----------------------------------------------------
extern "C" void kernel_launch(void* const* d_in, const int* in_sizes, int n_in,
                              void* d_out, int out_size) {
    const float* x      = (const float*)d_in[0];
    const float* l1_W   = (const float*)d_in[1];
    const float* l1_U   = (const float*)d_in[2];
    const float* l1_b   = (const float*)d_in[3];
    const float* l1_Wb  = (const float*)d_in[4];
    const float* l1_Ub  = (const float*)d_in[5];
    const float* l1_bb  = (const float*)d_in[6];
    const float* l2_Wx  = (const float*)d_in[7];
    const float* l2_Wh  = (const float*)d_in[8];
    const float* l2_U   = (const float*)d_in[9];
    const float* l2_b   = (const float*)d_in[10];
    const float* l2_Wxb = (const float*)d_in[11];
    const float* l2_Whb = (const float*)d_in[12];
    const float* l2_Ub  = (const float*)d_in[13];
    const float* l2_bb  = (const float*)d_in[14];
    float* out = (float*)d_out;

    k_init<<<32, 256>>>();

    dim3 gg(8, 256, 2);   // n-tiles, m-tiles, dir
    k_gemm<<<gg, 256>>>(x, l1_W, l1_Wb, nullptr, nullptr, l1_b, l1_bb, 1);
    k_recur1<<<128, 256>>>(l1_U, l1_Ub);
    k_gemm<<<gg, 256>>>(x, l2_Wx, l2_Wxb, l2_Wh, l2_Whb, nullptr, nullptr, 2);
    k_recur2<<<128, 256>>>(l2_U, l2_Ub, l2_b, l2_bb, out);
}